// round 1
// baseline (speedup 1.0000x reference)
#include <cuda_runtime.h>

// Problem constants
#define B_      2
#define L_      2048
#define D_      1024
#define H_      16
#define HD_     64
#define CHUNK_  128
#define M_ROWS  (B_ * L_)          // 4096
#define QKV_N   (3 * D_)           // 3072

// Scratch (device globals — no allocation allowed in kernel_launch)
__device__ __align__(16) float g_q[(size_t)B_ * H_ * L_ * HD_];
__device__ __align__(16) float g_k[(size_t)B_ * H_ * L_ * HD_];
__device__ __align__(16) float g_v[(size_t)B_ * H_ * L_ * HD_];
__device__ __align__(16) float g_ctx[(size_t)B_ * L_ * D_];

// ---------------------------------------------------------------------------
// Tiled SGEMM: C[M,N] = A[M,K] @ B[K,N] + bias[N]
// BM=BN=128, BK=16, 256 threads, 8x8 per-thread microtile.
// qkv_mode=1: scatter output into g_q/g_k/g_v with layout [b,h,l,d].
// ---------------------------------------------------------------------------
__global__ __launch_bounds__(256) void sgemm_kernel(
    const float* __restrict__ A, const float* __restrict__ Bm,
    const float* __restrict__ bias, float* __restrict__ C,
    int M, int N, int K, int qkv_mode)
{
    __shared__ float As[16][132];   // transposed A tile, padded
    __shared__ float Bs[16][132];   // B tile, padded (132 keeps 16B alignment)

    const int tid = threadIdx.x;
    const int tx = tid & 15, ty = tid >> 4;
    const int bm = blockIdx.y * 128, bn = blockIdx.x * 128;

    float acc[8][8];
#pragma unroll
    for (int i = 0; i < 8; i++)
#pragma unroll
        for (int j = 0; j < 8; j++) acc[i][j] = 0.f;

    for (int k0 = 0; k0 < K; k0 += 16) {
        // Load A tile (128 rows x 16 cols), store transposed
#pragma unroll
        for (int i = 0; i < 2; i++) {
            int idx = tid + i * 256;        // 0..511
            int row = idx >> 2;             // 0..127
            int c4  = (idx & 3) << 2;       // 0,4,8,12
            const float4 a4 = *reinterpret_cast<const float4*>(
                A + (size_t)(bm + row) * K + k0 + c4);
            As[c4 + 0][row] = a4.x;
            As[c4 + 1][row] = a4.y;
            As[c4 + 2][row] = a4.z;
            As[c4 + 3][row] = a4.w;
        }
        // Load B tile (16 rows x 128 cols)
#pragma unroll
        for (int i = 0; i < 2; i++) {
            int idx = tid + i * 256;        // 0..511
            int row = idx >> 5;             // 0..15
            int c4  = (idx & 31) << 2;      // 0..124
            *reinterpret_cast<float4*>(&Bs[row][c4]) =
                *reinterpret_cast<const float4*>(Bm + (size_t)(k0 + row) * N + bn + c4);
        }
        __syncthreads();

#pragma unroll
        for (int kk = 0; kk < 16; kk++) {
            float a[8], b[8];
#pragma unroll
            for (int i = 0; i < 8; i++) a[i] = As[kk][ty * 8 + i];
#pragma unroll
            for (int j = 0; j < 8; j++) b[j] = Bs[kk][tx * 8 + j];
#pragma unroll
            for (int i = 0; i < 8; i++)
#pragma unroll
                for (int j = 0; j < 8; j++) acc[i][j] += a[i] * b[j];
        }
        __syncthreads();
    }

    // Epilogue
#pragma unroll
    for (int i = 0; i < 8; i++) {
        const int m = bm + ty * 8 + i;
#pragma unroll
        for (int j = 0; j < 8; j++) {
            const int n = bn + tx * 8 + j;
            const float v = acc[i][j] + bias[n];
            if (qkv_mode) {
                // column decomposes as (which, h, dd); row as (b, l)
                const int which = n >> 10;
                const int h  = (n >> 6) & 15;
                const int dd = n & 63;
                const int b  = m >> 11;
                const int l  = m & 2047;
                const size_t dst = ((((size_t)b * H_ + h) * L_) + l) * HD_ + dd;
                float* tgt = (which == 0) ? g_q : (which == 1) ? g_k : g_v;
                tgt[dst] = v;
            } else {
                C[(size_t)m * N + n] = v;
            }
        }
    }
}

// ---------------------------------------------------------------------------
// Block-causal flash attention. grid = (16 q-chunks, 32 b*h), 128 threads.
// Thread r owns query row qc*128+r. K/V tiles (128x64 each) staged in smem.
// All smem reads in the hot loops are warp-uniform -> broadcast (no conflicts).
// ---------------------------------------------------------------------------
__global__ __launch_bounds__(128) void attn_kernel(float* __restrict__ ctx)
{
    extern __shared__ float sm[];
    float4* Ks4 = reinterpret_cast<float4*>(sm);            // 128*16 float4
    float4* Vs4 = reinterpret_cast<float4*>(sm + 128 * 64); // 128*16 float4

    const int qc = blockIdx.x;
    const int bh = blockIdx.y;
    const int r  = threadIdx.x;
    const int b  = bh >> 4, h = bh & 15;
    const size_t head_base = (size_t)bh * L_ * HD_;
    const int l = qc * CHUNK_ + r;

    // q row in registers, pre-scaled by 1/sqrt(64)
    const float scale = 0.125f;
    float q[64];
#pragma unroll
    for (int t = 0; t < 16; t++) {
        float4 q4 = *reinterpret_cast<const float4*>(&g_q[head_base + (size_t)l * HD_ + t * 4]);
        q[t * 4 + 0] = q4.x * scale;
        q[t * 4 + 1] = q4.y * scale;
        q[t * 4 + 2] = q4.z * scale;
        q[t * 4 + 3] = q4.w * scale;
    }

    float o[64];
#pragma unroll
    for (int dd = 0; dd < 64; dd++) o[dd] = 0.f;
    float m_run = -1e30f, lsum = 0.f;

    for (int kc = 0; kc <= qc; kc++) {
        const float4* kg = reinterpret_cast<const float4*>(&g_k[head_base + (size_t)kc * CHUNK_ * HD_]);
        const float4* vg = reinterpret_cast<const float4*>(&g_v[head_base + (size_t)kc * CHUNK_ * HD_]);
#pragma unroll
        for (int i = 0; i < 16; i++) {
            const int idx = r + i * 128;    // 0..2047
            Ks4[idx] = kg[idx];
            Vs4[idx] = vg[idx];
        }
        __syncthreads();

#pragma unroll 1
        for (int sub = 0; sub < 4; sub++) {
            float s[32];
            float smax = -1e30f;
#pragma unroll 4
            for (int jj = 0; jj < 32; jj++) {
                const float4* krow = Ks4 + (sub * 32 + jj) * 16;
                float a0 = 0.f, a1 = 0.f, a2 = 0.f, a3 = 0.f;
#pragma unroll
                for (int t = 0; t < 16; t += 4) {
                    float4 k0 = krow[t + 0];
                    float4 k1 = krow[t + 1];
                    float4 k2 = krow[t + 2];
                    float4 k3 = krow[t + 3];
                    a0 += q[(t + 0) * 4 + 0] * k0.x + q[(t + 0) * 4 + 1] * k0.y
                        + q[(t + 0) * 4 + 2] * k0.z + q[(t + 0) * 4 + 3] * k0.w;
                    a1 += q[(t + 1) * 4 + 0] * k1.x + q[(t + 1) * 4 + 1] * k1.y
                        + q[(t + 1) * 4 + 2] * k1.z + q[(t + 1) * 4 + 3] * k1.w;
                    a2 += q[(t + 2) * 4 + 0] * k2.x + q[(t + 2) * 4 + 1] * k2.y
                        + q[(t + 2) * 4 + 2] * k2.z + q[(t + 2) * 4 + 3] * k2.w;
                    a3 += q[(t + 3) * 4 + 0] * k3.x + q[(t + 3) * 4 + 1] * k3.y
                        + q[(t + 3) * 4 + 2] * k3.z + q[(t + 3) * 4 + 3] * k3.w;
                }
                const float sv = (a0 + a1) + (a2 + a3);
                s[jj] = sv;
                smax = fmaxf(smax, sv);
            }

            const float m_new = fmaxf(m_run, smax);
            const float corr = __expf(m_run - m_new);   // 0 on first tile
            lsum *= corr;
#pragma unroll
            for (int dd = 0; dd < 64; dd++) o[dd] *= corr;

#pragma unroll 4
            for (int jj = 0; jj < 32; jj++) {
                const float p = __expf(s[jj] - m_new);
                lsum += p;
                const float4* vrow = Vs4 + (sub * 32 + jj) * 16;
#pragma unroll
                for (int t = 0; t < 16; t++) {
                    float4 v4 = vrow[t];
                    o[t * 4 + 0] += p * v4.x;
                    o[t * 4 + 1] += p * v4.y;
                    o[t * 4 + 2] += p * v4.z;
                    o[t * 4 + 3] += p * v4.w;
                }
            }
            m_run = m_new;
        }
        __syncthreads();
    }

    const float inv = 1.f / lsum;
    float* outp = &ctx[((size_t)b * L_ + l) * D_ + h * HD_];
#pragma unroll
    for (int t = 0; t < 16; t++) {
        float4 ov;
        ov.x = o[t * 4 + 0] * inv;
        ov.y = o[t * 4 + 1] * inv;
        ov.z = o[t * 4 + 2] * inv;
        ov.w = o[t * 4 + 3] * inv;
        *reinterpret_cast<float4*>(outp + t * 4) = ov;
    }
}

// ---------------------------------------------------------------------------
extern "C" void kernel_launch(void* const* d_in, const int* in_sizes, int n_in,
                              void* d_out, int out_size)
{
    const float* x    = (const float*)d_in[0];   // [B,L,D]
    const float* Wqkv = (const float*)d_in[1];   // [D, 3D]
    const float* bqkv = (const float*)d_in[2];   // [3D]
    const float* Wout = (const float*)d_in[3];   // [D, D]
    const float* bout = (const float*)d_in[4];   // [D]
    float* out = (float*)d_out;                  // [B,L,D]

    (void)in_sizes; (void)n_in; (void)out_size;

    static bool attr_set = false;
    // idempotent + immediate (not stream-ordered); safe under capture
    cudaFuncSetAttribute(attn_kernel, cudaFuncAttributeMaxDynamicSharedMemorySize, 65536);
    (void)attr_set;

    float* ctx_ptr = nullptr;
    cudaGetSymbolAddress((void**)&ctx_ptr, g_ctx);

    // 1. QKV projection + scatter to [b,h,l,d]
    {
        dim3 grid(QKV_N / 128, M_ROWS / 128);   // (24, 32)
        sgemm_kernel<<<grid, 256>>>(x, Wqkv, bqkv, nullptr,
                                    M_ROWS, QKV_N, D_, 1);
    }
    // 2. Block-causal attention -> g_ctx [b,l,(h d)]
    {
        dim3 grid(L_ / CHUNK_, B_ * H_);        // (16, 32)
        attn_kernel<<<grid, 128, 65536>>>(ctx_ptr);
    }
    // 3. Output projection -> d_out
    {
        dim3 grid(D_ / 128, M_ROWS / 128);      // (8, 32)
        sgemm_kernel<<<grid, 256>>>(ctx_ptr, Wout, bout, out,
                                    M_ROWS, D_, D_, 0);
    }
}

// round 3
// speedup vs baseline: 3.5410x; 3.5410x over previous
#include <cuda_runtime.h>
#include <cstdint>

// Problem constants
#define B_      2
#define L_      2048
#define D_      1024
#define H_      16
#define HD_     64
#define CHUNK_  128
#define M_ROWS  (B_ * L_)          // 4096
#define QKV_N   (3 * D_)           // 3072

// Scratch (device globals — no allocation allowed)
__device__ __align__(16) float g_q[(size_t)B_ * H_ * L_ * HD_];
__device__ __align__(16) float g_k[(size_t)B_ * H_ * L_ * HD_];
__device__ __align__(16) float g_v[(size_t)B_ * H_ * L_ * HD_];
__device__ __align__(16) float g_ctx[(size_t)B_ * L_ * D_];

// ===========================================================================
// Helpers (baseline PTX only — no 'a'-feature instructions)
// ===========================================================================
__device__ __forceinline__ uint32_t smem_u32(const void* p) {
    uint32_t a;
    asm("{ .reg .u64 t; cvta.to.shared.u64 t, %1; cvt.u32.u64 %0, t; }" : "=r"(a) : "l"(p));
    return a;
}
// round-to-nearest tf32 (returns b32 bit pattern with low mantissa zeroed)
__device__ __forceinline__ uint32_t f2tf(float x) {
    uint32_t r;
    asm("cvt.rna.tf32.f32 %0, %1;" : "=r"(r) : "f"(x));
    return r;
}
__device__ __forceinline__ float f2tff(float x) { return __uint_as_float(f2tf(x)); }

// m16n8k8 tf32 mma: D = A*B + D  (A row-major, B col-major)
__device__ __forceinline__ void mma8(float* c, const uint32_t* a, const uint32_t* b) {
    asm volatile(
        "mma.sync.aligned.m16n8k8.row.col.f32.tf32.tf32.f32 "
        "{%0,%1,%2,%3}, {%4,%5,%6,%7}, {%8,%9}, {%0,%1,%2,%3};"
        : "+f"(c[0]), "+f"(c[1]), "+f"(c[2]), "+f"(c[3])
        : "r"(a[0]), "r"(a[1]), "r"(a[2]), "r"(a[3]), "r"(b[0]), "r"(b[1]));
}

__device__ __forceinline__ void cp16(uint32_t dst, const void* src) {
    asm volatile("cp.async.cg.shared.global [%0], [%1], 16;" :: "r"(dst), "l"(src));
}
#define CP_COMMIT() asm volatile("cp.async.commit_group;" ::: "memory")
#define CP_WAIT0()  asm volatile("cp.async.wait_group 0;" ::: "memory")

// ===========================================================================
// tf32 mma GEMM: C[M,N] = A[M,K] @ W[K,N] + bias
// 128x128 CTA tile, BK=32, 256 thr (8 warps as 2x4, warp tile 64x32).
// Register-staged double buffer; cvt.rna.tf32 during smem staging.
// qkv_mode=1: scatter into g_q/g_k/g_v [b,h,l,d] (values tf32-rounded).
// ===========================================================================
#define GA_STRIDE 36
#define GB_STRIDE 132
#define GA_STAGE  (128 * GA_STRIDE)           // floats
#define GB_STAGE  (32 * GB_STRIDE)
#define GB_OFF    (2 * GA_STAGE * 4)          // bytes
#define GEMM_SMEM (GB_OFF + 2 * GB_STAGE * 4) // 70656 bytes

__global__ __launch_bounds__(256) void gemm_mma_kernel(
    const float* __restrict__ A, const float* __restrict__ W,
    const float* __restrict__ bias, float* __restrict__ C,
    int M, int N, int K, int qkv_mode)
{
    extern __shared__ __align__(16) char sm[];
    const int tid = threadIdx.x, wid = tid >> 5, lane = tid & 31;
    const int g = lane >> 2, tq = lane & 3;
    const int bm = blockIdx.y * 128, bn = blockIdx.x * 128;
    const int wm = (wid >> 2) * 64, wn = (wid & 3) * 32;

    float c[4][4][4];
#pragma unroll
    for (int mt = 0; mt < 4; mt++)
#pragma unroll
        for (int nt = 0; nt < 4; nt++)
#pragma unroll
            for (int i = 0; i < 4; i++) c[mt][nt][i] = 0.f;

    const int KT = K >> 5;
    float4 ra[4], rb[4];

    // prologue load
#pragma unroll
    for (int i = 0; i < 4; i++) {
        const int idx = tid + i * 256;
        ra[i] = *(const float4*)(A + (size_t)(bm + (idx >> 3)) * K + (idx & 7) * 4);
        rb[i] = *(const float4*)(W + (size_t)(idx >> 5) * N + bn + (idx & 31) * 4);
    }

    int s = 0;
    for (int t = 0; t < KT; t++) {
        // store staged regs -> smem (with tf32 rounding)
        {
            float* As = (float*)sm + s * GA_STAGE;
            float* Bs = (float*)(sm + GB_OFF) + s * GB_STAGE;
#pragma unroll
            for (int i = 0; i < 4; i++) {
                const int idx = tid + i * 256;
                float* ap = As + (idx >> 3) * GA_STRIDE + (idx & 7) * 4;
                ap[0] = f2tff(ra[i].x); ap[1] = f2tff(ra[i].y);
                ap[2] = f2tff(ra[i].z); ap[3] = f2tff(ra[i].w);
                float* bp = Bs + (idx >> 5) * GB_STRIDE + (idx & 31) * 4;
                bp[0] = f2tff(rb[i].x); bp[1] = f2tff(rb[i].y);
                bp[2] = f2tff(rb[i].z); bp[3] = f2tff(rb[i].w);
            }
        }
        __syncthreads();
        if (t + 1 < KT) {
            const int k0 = (t + 1) * 32;
#pragma unroll
            for (int i = 0; i < 4; i++) {
                const int idx = tid + i * 256;
                ra[i] = *(const float4*)(A + (size_t)(bm + (idx >> 3)) * K + k0 + (idx & 7) * 4);
                rb[i] = *(const float4*)(W + (size_t)(k0 + (idx >> 5)) * N + bn + (idx & 31) * 4);
            }
        }
        // compute on stage s
        {
            const float* As = (const float*)sm + s * GA_STAGE;
            const float* Bs = (const float*)(sm + GB_OFF) + s * GB_STAGE;
#pragma unroll
            for (int kb = 0; kb < 4; kb++) {
                uint32_t af[4][4], bf[4][2];
#pragma unroll
                for (int mt = 0; mt < 4; mt++) {
                    const float* ap = As + (wm + mt * 16 + g) * GA_STRIDE + kb * 8 + tq;
                    af[mt][0] = __float_as_uint(ap[0]);
                    af[mt][1] = __float_as_uint(ap[8 * GA_STRIDE]);
                    af[mt][2] = __float_as_uint(ap[4]);
                    af[mt][3] = __float_as_uint(ap[8 * GA_STRIDE + 4]);
                }
#pragma unroll
                for (int nt = 0; nt < 4; nt++) {
                    const float* bp = Bs + (kb * 8 + tq) * GB_STRIDE + wn + nt * 8 + g;
                    bf[nt][0] = __float_as_uint(bp[0]);
                    bf[nt][1] = __float_as_uint(bp[4 * GB_STRIDE]);
                }
#pragma unroll
                for (int mt = 0; mt < 4; mt++)
#pragma unroll
                    for (int nt = 0; nt < 4; nt++)
                        mma8(c[mt][nt], af[mt], bf[nt]);
            }
        }
        s ^= 1;
    }

    // Epilogue: C frag c0:(g,2tq) c1:(g,2tq+1) c2:(g+8,2tq) c3:(g+8,2tq+1)
#pragma unroll
    for (int mt = 0; mt < 4; mt++) {
#pragma unroll
        for (int nt = 0; nt < 4; nt++) {
            const int col = bn + wn + nt * 8 + 2 * tq;
            const float b0 = bias[col], b1 = bias[col + 1];
            const int r0 = bm + wm + mt * 16 + g;
            float v00 = c[mt][nt][0] + b0, v01 = c[mt][nt][1] + b1;
            float v10 = c[mt][nt][2] + b0, v11 = c[mt][nt][3] + b1;
            if (qkv_mode) {
                // round to tf32 here so attention needs no per-use conversion
                v00 = f2tff(v00); v01 = f2tff(v01);
                v10 = f2tff(v10); v11 = f2tff(v11);
                const int which = col >> 10;
                const int h  = (col >> 6) & 15;
                const int dd = col & 63;
                float* tgt = (which == 0) ? g_q : (which == 1) ? g_k : g_v;
                const int b_lo = r0 >> 11, l_lo = r0 & 2047;
                float* d0 = tgt + ((((size_t)b_lo * H_ + h) * L_) + l_lo) * HD_ + dd;
                *(float2*)d0 = make_float2(v00, v01);
                const int r1 = r0 + 8;
                const int b_hi = r1 >> 11, l_hi = r1 & 2047;
                float* d1 = tgt + ((((size_t)b_hi * H_ + h) * L_) + l_hi) * HD_ + dd;
                *(float2*)d1 = make_float2(v10, v11);
            } else {
                *(float2*)(C + (size_t)r0 * N + col)       = make_float2(v00, v01);
                *(float2*)(C + (size_t)(r0 + 8) * N + col) = make_float2(v10, v11);
            }
        }
    }
}

// ===========================================================================
// Block-causal flash attention on mma.sync tf32.
// grid = (16 qc reversed, 32 bh), 256 threads (8 warps x m16 rows).
// K/V double-buffered via cp.async (inputs pre-rounded to tf32 by QKV epi).
// P round-trips through per-warp padded smem.
// ===========================================================================
#define KV_STRIDE  68
#define KV_STAGE_B (128 * KV_STRIDE * 4)   // 34816 bytes
#define AT_VOFF    (2 * KV_STAGE_B)        // 69632
#define AT_POFF    (4 * KV_STAGE_B)        // 139264
#define P_STRIDE   132
#define P_WARP_B   (16 * P_STRIDE * 4)     // 8448
#define ATTN_SMEM  (AT_POFF + 8 * P_WARP_B) // 206848 bytes

__global__ __launch_bounds__(256) void attn_mma_kernel(float* __restrict__ ctx)
{
    extern __shared__ __align__(16) char sm[];
    const int tid = threadIdx.x, wid = tid >> 5, lane = tid & 31;
    const int g = lane >> 2, tq = lane & 3;
    const int qc = 15 - (int)blockIdx.x;      // heavy chunks first
    const int bh = blockIdx.y, b = bh >> 4, h = bh & 15;
    const size_t head = (size_t)bh * L_ * HD_;
    const int m0 = wid * 16;
    const uint32_t sb = smem_u32(sm);
    float* Pw = (float*)(sm + AT_POFF + wid * P_WARP_B);

    // Q fragments (already tf32-rounded in gmem); fold in 1/sqrt(64)
    uint32_t qa[8][4];
    {
        const float* qb = g_q + head + (size_t)(qc * CHUNK_ + m0) * HD_;
#pragma unroll
        for (int kb = 0; kb < 8; kb++) {
            qa[kb][0] = __float_as_uint(qb[g * 64 + kb * 8 + tq] * 0.125f);
            qa[kb][1] = __float_as_uint(qb[(g + 8) * 64 + kb * 8 + tq] * 0.125f);
            qa[kb][2] = __float_as_uint(qb[g * 64 + kb * 8 + tq + 4] * 0.125f);
            qa[kb][3] = __float_as_uint(qb[(g + 8) * 64 + kb * 8 + tq + 4] * 0.125f);
        }
    }

    float o[8][4];
#pragma unroll
    for (int nv = 0; nv < 8; nv++)
#pragma unroll
        for (int i = 0; i < 4; i++) o[nv][i] = 0.f;
    float m_lo = -1e30f, m_hi = -1e30f, ls_lo = 0.f, ls_hi = 0.f;

    // prologue: stage kc=0 into buffer 0
    {
        const float* kg = g_k + head;
        const float* vg = g_v + head;
#pragma unroll
        for (int i = 0; i < 8; i++) {
            const int idx = tid + i * 256;
            const int row = idx >> 4, c4 = idx & 15;
            cp16(sb + row * (KV_STRIDE * 4) + c4 * 16, kg + row * 64 + c4 * 4);
            cp16(sb + AT_VOFF + row * (KV_STRIDE * 4) + c4 * 16, vg + row * 64 + c4 * 4);
        }
        CP_COMMIT();
    }

    int s = 0;
    for (int kc = 0; kc <= qc; kc++) {
        CP_WAIT0();
        __syncthreads();
        if (kc < qc) {
            const float* kg = g_k + head + (size_t)(kc + 1) * CHUNK_ * HD_;
            const float* vg = g_v + head + (size_t)(kc + 1) * CHUNK_ * HD_;
            const uint32_t st = (uint32_t)(s ^ 1) * KV_STAGE_B;
#pragma unroll
            for (int i = 0; i < 8; i++) {
                const int idx = tid + i * 256;
                const int row = idx >> 4, c4 = idx & 15;
                cp16(sb + st + row * (KV_STRIDE * 4) + c4 * 16, kg + row * 64 + c4 * 4);
                cp16(sb + AT_VOFF + st + row * (KV_STRIDE * 4) + c4 * 16, vg + row * 64 + c4 * 4);
            }
            CP_COMMIT();
        }
        const float* Ks = (const float*)(sm + s * KV_STAGE_B);
        const float* Vs = (const float*)(sm + AT_VOFF + s * KV_STAGE_B);

        // S = Q K^T  (m16 x n128, k64)
        float sc[16][4];
#pragma unroll
        for (int nt = 0; nt < 16; nt++) {
            sc[nt][0] = sc[nt][1] = sc[nt][2] = sc[nt][3] = 0.f;
            const float* kp = Ks + (nt * 8 + g) * KV_STRIDE;
#pragma unroll
            for (int kb = 0; kb < 8; kb++) {
                uint32_t bfr[2];
                bfr[0] = __float_as_uint(kp[kb * 8 + tq]);
                bfr[1] = __float_as_uint(kp[kb * 8 + tq + 4]);
                mma8(sc[nt], qa[kb], bfr);
            }
        }

        // online softmax (rows g / g+8 owned by 4-lane groups)
        float smx_lo = -1e30f, smx_hi = -1e30f;
#pragma unroll
        for (int nt = 0; nt < 16; nt++) {
            smx_lo = fmaxf(smx_lo, fmaxf(sc[nt][0], sc[nt][1]));
            smx_hi = fmaxf(smx_hi, fmaxf(sc[nt][2], sc[nt][3]));
        }
        smx_lo = fmaxf(smx_lo, __shfl_xor_sync(0xffffffffu, smx_lo, 1));
        smx_lo = fmaxf(smx_lo, __shfl_xor_sync(0xffffffffu, smx_lo, 2));
        smx_hi = fmaxf(smx_hi, __shfl_xor_sync(0xffffffffu, smx_hi, 1));
        smx_hi = fmaxf(smx_hi, __shfl_xor_sync(0xffffffffu, smx_hi, 2));
        const float mn_lo = fmaxf(m_lo, smx_lo), mn_hi = fmaxf(m_hi, smx_hi);
        const float corr_lo = __expf(m_lo - mn_lo), corr_hi = __expf(m_hi - mn_hi);
        m_lo = mn_lo; m_hi = mn_hi;
        ls_lo *= corr_lo; ls_hi *= corr_hi;

        __syncwarp();   // prior PV reads of Pw complete before overwrite
#pragma unroll
        for (int nt = 0; nt < 16; nt++) {
            const float p0 = __expf(sc[nt][0] - mn_lo), p1 = __expf(sc[nt][1] - mn_lo);
            const float p2 = __expf(sc[nt][2] - mn_hi), p3 = __expf(sc[nt][3] - mn_hi);
            ls_lo += p0 + p1; ls_hi += p2 + p3;
            *(float2*)(Pw + g * P_STRIDE + nt * 8 + 2 * tq) =
                make_float2(f2tff(p0), f2tff(p1));
            *(float2*)(Pw + (g + 8) * P_STRIDE + nt * 8 + 2 * tq) =
                make_float2(f2tff(p2), f2tff(p3));
        }
        __syncwarp();

#pragma unroll
        for (int nv = 0; nv < 8; nv++) {
            o[nv][0] *= corr_lo; o[nv][1] *= corr_lo;
            o[nv][2] *= corr_hi; o[nv][3] *= corr_hi;
        }

        // O += P V  (m16 x n64, k128)
#pragma unroll
        for (int kb = 0; kb < 16; kb++) {
            uint32_t pa[4];
            pa[0] = __float_as_uint(Pw[g * P_STRIDE + kb * 8 + tq]);
            pa[1] = __float_as_uint(Pw[(g + 8) * P_STRIDE + kb * 8 + tq]);
            pa[2] = __float_as_uint(Pw[g * P_STRIDE + kb * 8 + tq + 4]);
            pa[3] = __float_as_uint(Pw[(g + 8) * P_STRIDE + kb * 8 + tq + 4]);
#pragma unroll
            for (int nv = 0; nv < 8; nv++) {
                uint32_t vb[2];
                vb[0] = __float_as_uint(Vs[(kb * 8 + tq) * KV_STRIDE + nv * 8 + g]);
                vb[1] = __float_as_uint(Vs[(kb * 8 + tq + 4) * KV_STRIDE + nv * 8 + g]);
                mma8(o[nv], pa, vb);
            }
        }
        s ^= 1;
    }

    ls_lo += __shfl_xor_sync(0xffffffffu, ls_lo, 1);
    ls_lo += __shfl_xor_sync(0xffffffffu, ls_lo, 2);
    ls_hi += __shfl_xor_sync(0xffffffffu, ls_hi, 1);
    ls_hi += __shfl_xor_sync(0xffffffffu, ls_hi, 2);
    const float il = 1.f / ls_lo, ih = 1.f / ls_hi;

    const int r0 = qc * CHUNK_ + m0 + g;
#pragma unroll
    for (int nv = 0; nv < 8; nv++) {
        const int col = h * HD_ + nv * 8 + 2 * tq;
        *(float2*)(ctx + ((size_t)b * L_ + r0) * D_ + col) =
            make_float2(o[nv][0] * il, o[nv][1] * il);
        *(float2*)(ctx + ((size_t)b * L_ + r0 + 8) * D_ + col) =
            make_float2(o[nv][2] * ih, o[nv][3] * ih);
    }
}

// ---------------------------------------------------------------------------
extern "C" void kernel_launch(void* const* d_in, const int* in_sizes, int n_in,
                              void* d_out, int out_size)
{
    const float* x    = (const float*)d_in[0];
    const float* Wqkv = (const float*)d_in[1];
    const float* bqkv = (const float*)d_in[2];
    const float* Wout = (const float*)d_in[3];
    const float* bout = (const float*)d_in[4];
    float* out = (float*)d_out;

    (void)in_sizes; (void)n_in; (void)out_size;

    cudaFuncSetAttribute(gemm_mma_kernel, cudaFuncAttributeMaxDynamicSharedMemorySize, GEMM_SMEM);
    cudaFuncSetAttribute(attn_mma_kernel, cudaFuncAttributeMaxDynamicSharedMemorySize, ATTN_SMEM);

    float* ctx_ptr = nullptr;
    cudaGetSymbolAddress((void**)&ctx_ptr, g_ctx);

    // 1. QKV projection (mma tf32) + scatter to [b,h,l,d], tf32-rounded
    {
        dim3 grid(QKV_N / 128, M_ROWS / 128);   // (24, 32)
        gemm_mma_kernel<<<grid, 256, GEMM_SMEM>>>(x, Wqkv, bqkv, nullptr,
                                                  M_ROWS, QKV_N, D_, 1);
    }
    // 2. Block-causal attention -> g_ctx
    {
        dim3 grid(L_ / CHUNK_, B_ * H_);        // (16, 32)
        attn_mma_kernel<<<grid, 256, ATTN_SMEM>>>(ctx_ptr);
    }
    // 3. Output projection -> d_out
    {
        dim3 grid(D_ / 128, M_ROWS / 128);      // (8, 32)
        gemm_mma_kernel<<<grid, 256, GEMM_SMEM>>>(ctx_ptr, Wout, bout, out,
                                                  M_ROWS, D_, D_, 0);
    }
}

// round 4
// speedup vs baseline: 3.6428x; 1.0287x over previous
#include <cuda_runtime.h>
#include <cstdint>

// Problem constants
#define B_      2
#define L_      2048
#define D_      1024
#define H_      16
#define HD_     64
#define CHUNK_  128
#define M_ROWS  (B_ * L_)          // 4096
#define QKV_N   (3 * D_)           // 3072

// Scratch (device globals — no allocation allowed)
__device__ __align__(16) float g_q[(size_t)B_ * H_ * L_ * HD_];
__device__ __align__(16) float g_k[(size_t)B_ * H_ * L_ * HD_];
__device__ __align__(16) float g_v[(size_t)B_ * H_ * L_ * HD_];
__device__ __align__(16) float g_ctx[(size_t)B_ * L_ * D_];
__device__ __align__(16) float g_xr[(size_t)M_ROWS * D_];
__device__ __align__(16) float g_wqkvr[(size_t)D_ * QKV_N];
__device__ __align__(16) float g_woutr[(size_t)D_ * D_];

// ===========================================================================
// Helpers (baseline PTX only — no 'a'-feature instructions)
// ===========================================================================
__device__ __forceinline__ uint32_t smem_u32(const void* p) {
    uint32_t a;
    asm("{ .reg .u64 t; cvta.to.shared.u64 t, %1; cvt.u32.u64 %0, t; }" : "=r"(a) : "l"(p));
    return a;
}
__device__ __forceinline__ uint32_t f2tf(float x) {
    uint32_t r;
    asm("cvt.rna.tf32.f32 %0, %1;" : "=r"(r) : "f"(x));
    return r;
}
__device__ __forceinline__ float f2tff(float x) { return __uint_as_float(f2tf(x)); }

// m16n8k8 tf32 mma: D = A*B + D  (A row-major, B col-major)
__device__ __forceinline__ void mma8(float* c, const uint32_t* a, const uint32_t* b) {
    asm volatile(
        "mma.sync.aligned.m16n8k8.row.col.f32.tf32.tf32.f32 "
        "{%0,%1,%2,%3}, {%4,%5,%6,%7}, {%8,%9}, {%0,%1,%2,%3};"
        : "+f"(c[0]), "+f"(c[1]), "+f"(c[2]), "+f"(c[3])
        : "r"(a[0]), "r"(a[1]), "r"(a[2]), "r"(a[3]), "r"(b[0]), "r"(b[1]));
}

__device__ __forceinline__ void cp16(uint32_t dst, const void* src) {
    asm volatile("cp.async.cg.shared.global [%0], [%1], 16;" :: "r"(dst), "l"(src));
}
#define CP_COMMIT() asm volatile("cp.async.commit_group;" ::: "memory")
#define CP_WAIT0()  asm volatile("cp.async.wait_group 0;" ::: "memory")
#define CP_WAIT1()  asm volatile("cp.async.wait_group 1;" ::: "memory")

// ===========================================================================
// Pre-round pass: fp32 -> tf32-rounded fp32 (vectorized)
// ===========================================================================
__global__ __launch_bounds__(256) void tf32_round_kernel(
    const float4* __restrict__ in, float4* __restrict__ out, int n4)
{
    const int i = blockIdx.x * blockDim.x + threadIdx.x;
    if (i < n4) {
        float4 v = in[i];
        v.x = f2tff(v.x); v.y = f2tff(v.y);
        v.z = f2tff(v.z); v.w = f2tff(v.w);
        out[i] = v;
    }
}

// ===========================================================================
// tf32 mma GEMM: C[M,N] = A[M,K] @ W[K,N] + bias   (A, W pre-rounded to tf32)
// 128x128 CTA tile, BK=32, 256 thr (8 warps 2x4, warp tile 64x32).
// 2-stage cp.async pipeline; 2 CTAs/SM.
// qkv_mode=1: scatter into g_q/g_k/g_v [b,h,l,d] (tf32-rounded).
// ===========================================================================
#define GS_A 36
#define GS_B 132
#define GSTAGE_A_B (128 * GS_A * 4)   // 18432 bytes
#define GSTAGE_B_B (32 * GS_B * 4)    // 16896 bytes
#define G_BOFF     (2 * GSTAGE_A_B)
#define GEMM_SMEM  (2 * (GSTAGE_A_B + GSTAGE_B_B))   // 70656 bytes

__device__ __forceinline__ void gemm_prefetch(
    uint32_t sb, int s, const float* A, const float* W,
    int K, int N, int bm, int bn, int k0, int tid)
{
    const uint32_t a_st = sb + (uint32_t)s * GSTAGE_A_B;
    const uint32_t b_st = sb + G_BOFF + (uint32_t)s * GSTAGE_B_B;
#pragma unroll
    for (int i = 0; i < 4; i++) {
        const int idx = tid + i * 256;
        const int r = idx >> 3, c = idx & 7;
        cp16(a_st + r * (GS_A * 4) + c * 16, A + (size_t)(bm + r) * K + k0 + c * 4);
    }
#pragma unroll
    for (int i = 0; i < 4; i++) {
        const int idx = tid + i * 256;
        const int r = idx >> 5, c = idx & 31;
        cp16(b_st + r * (GS_B * 4) + c * 16, W + (size_t)(k0 + r) * N + bn + c * 4);
    }
}

__global__ __launch_bounds__(256, 2) void gemm_mma_kernel(
    const float* __restrict__ A, const float* __restrict__ W,
    const float* __restrict__ bias, float* __restrict__ C,
    int M, int N, int K, int qkv_mode)
{
    extern __shared__ __align__(16) char sm[];
    const uint32_t sb = smem_u32(sm);
    const int tid = threadIdx.x, wid = tid >> 5, lane = tid & 31;
    const int g = lane >> 2, tq = lane & 3;
    const int bm = blockIdx.y * 128, bn = blockIdx.x * 128;
    const int wm = (wid >> 2) * 64, wn = (wid & 3) * 32;

    float c[4][4][4];
#pragma unroll
    for (int mt = 0; mt < 4; mt++)
#pragma unroll
        for (int nt = 0; nt < 4; nt++)
#pragma unroll
            for (int i = 0; i < 4; i++) c[mt][nt][i] = 0.f;

    const int KT = K >> 5;
    gemm_prefetch(sb, 0, A, W, K, N, bm, bn, 0, tid);  CP_COMMIT();
    gemm_prefetch(sb, 1, A, W, K, N, bm, bn, 32, tid); CP_COMMIT();

    for (int t = 0; t < KT; t++) {
        CP_WAIT1();
        __syncthreads();
        const int s = t & 1;
        {
            const float* As = (const float*)(sm + (size_t)s * GSTAGE_A_B);
            const float* Bs = (const float*)(sm + G_BOFF + (size_t)s * GSTAGE_B_B);
#pragma unroll
            for (int kb = 0; kb < 4; kb++) {
                uint32_t af[4][4], bf[4][2];
#pragma unroll
                for (int mt = 0; mt < 4; mt++) {
                    const float* ap = As + (wm + mt * 16 + g) * GS_A + kb * 8 + tq;
                    af[mt][0] = __float_as_uint(ap[0]);
                    af[mt][1] = __float_as_uint(ap[8 * GS_A]);
                    af[mt][2] = __float_as_uint(ap[4]);
                    af[mt][3] = __float_as_uint(ap[8 * GS_A + 4]);
                }
#pragma unroll
                for (int nt = 0; nt < 4; nt++) {
                    const float* bp = Bs + (kb * 8 + tq) * GS_B + wn + nt * 8 + g;
                    bf[nt][0] = __float_as_uint(bp[0]);
                    bf[nt][1] = __float_as_uint(bp[4 * GS_B]);
                }
#pragma unroll
                for (int mt = 0; mt < 4; mt++)
#pragma unroll
                    for (int nt = 0; nt < 4; nt++)
                        mma8(c[mt][nt], af[mt], bf[nt]);
            }
        }
        __syncthreads();
        if (t + 2 < KT)
            gemm_prefetch(sb, s, A, W, K, N, bm, bn, (t + 2) * 32, tid);
        CP_COMMIT();
    }

    // Epilogue: c0:(g,2tq) c1:(g,2tq+1) c2:(g+8,2tq) c3:(g+8,2tq+1)
#pragma unroll
    for (int mt = 0; mt < 4; mt++) {
#pragma unroll
        for (int nt = 0; nt < 4; nt++) {
            const int col = bn + wn + nt * 8 + 2 * tq;
            const float b0 = bias[col], b1 = bias[col + 1];
            const int r0 = bm + wm + mt * 16 + g;
            float v00 = c[mt][nt][0] + b0, v01 = c[mt][nt][1] + b1;
            float v10 = c[mt][nt][2] + b0, v11 = c[mt][nt][3] + b1;
            if (qkv_mode) {
                v00 = f2tff(v00); v01 = f2tff(v01);
                v10 = f2tff(v10); v11 = f2tff(v11);
                const int which = col >> 10;
                const int h  = (col >> 6) & 15;
                const int dd = col & 63;
                float* tgt = (which == 0) ? g_q : (which == 1) ? g_k : g_v;
                const int b_lo = r0 >> 11, l_lo = r0 & 2047;
                *(float2*)(tgt + ((((size_t)b_lo * H_ + h) * L_) + l_lo) * HD_ + dd) =
                    make_float2(v00, v01);
                const int r1 = r0 + 8;
                const int b_hi = r1 >> 11, l_hi = r1 & 2047;
                *(float2*)(tgt + ((((size_t)b_hi * H_ + h) * L_) + l_hi) * HD_ + dd) =
                    make_float2(v10, v11);
            } else {
                *(float2*)(C + (size_t)r0 * N + col)       = make_float2(v00, v01);
                *(float2*)(C + (size_t)(r0 + 8) * N + col) = make_float2(v10, v11);
            }
        }
    }
}

// ===========================================================================
// Block-causal flash attention on mma.sync tf32.
// grid = (16 qc reversed, 32 bh), 256 threads (8 warps x m16 rows).
// K double-buffered + V single-buffered cp.async; P transposed C-frag->A-frag
// via intra-quad shuffles (no smem). 102 KB smem -> 2 CTAs/SM.
// ===========================================================================
#define KV_STRIDE  68
#define KV_STAGE_B (128 * KV_STRIDE * 4)   // 34816 bytes
#define AT_VOFF    (2 * KV_STAGE_B)        // 69632
#define ATTN_SMEM  (AT_VOFF + KV_STAGE_B)  // 104448 bytes

__device__ __forceinline__ void attn_prefetch(uint32_t dst_base, const float* src, int tid)
{
#pragma unroll
    for (int i = 0; i < 8; i++) {
        const int idx = tid + i * 256;
        const int row = idx >> 4, c4 = idx & 15;
        cp16(dst_base + row * (KV_STRIDE * 4) + c4 * 16, src + row * 64 + c4 * 4);
    }
}

__global__ __launch_bounds__(256, 2) void attn_mma_kernel(float* __restrict__ ctx)
{
    extern __shared__ __align__(16) char sm[];
    const uint32_t sb = smem_u32(sm);
    const int tid = threadIdx.x, wid = tid >> 5, lane = tid & 31;
    const int g = lane >> 2, tq = lane & 3;
    const int qc = 15 - (int)blockIdx.x;
    const int bh = blockIdx.y, b = bh >> 4, h = bh & 15;
    const size_t head = (size_t)bh * L_ * HD_;
    const int m0 = wid * 16;

    // shuffle-transpose constants
    const int sel  = tq & 1;
    const int srcA = (lane & ~3) | (tq >> 1);
    const int srcB = srcA + 2;

    // Q fragments (tf32-rounded in gmem); fold in 1/8 (exact pow2)
    uint32_t qa[8][4];
    {
        const float* qb = g_q + head + (size_t)(qc * CHUNK_ + m0) * HD_;
#pragma unroll
        for (int kb = 0; kb < 8; kb++) {
            qa[kb][0] = __float_as_uint(qb[g * 64 + kb * 8 + tq] * 0.125f);
            qa[kb][1] = __float_as_uint(qb[(g + 8) * 64 + kb * 8 + tq] * 0.125f);
            qa[kb][2] = __float_as_uint(qb[g * 64 + kb * 8 + tq + 4] * 0.125f);
            qa[kb][3] = __float_as_uint(qb[(g + 8) * 64 + kb * 8 + tq + 4] * 0.125f);
        }
    }

    float o[8][4];
#pragma unroll
    for (int nv = 0; nv < 8; nv++)
#pragma unroll
        for (int i = 0; i < 4; i++) o[nv][i] = 0.f;
    float m_lo = -1e30f, m_hi = -1e30f, ls_lo = 0.f, ls_hi = 0.f;

    // prologue: K(0) -> Kbuf0, V(0) -> Vbuf
    attn_prefetch(sb, g_k + head, tid);
    attn_prefetch(sb + AT_VOFF, g_v + head, tid);
    CP_COMMIT();

    int s = 0;
    for (int kc = 0; kc <= qc; kc++) {
        CP_WAIT0();
        __syncthreads();
        const float* Ks = (const float*)(sm + (size_t)s * KV_STAGE_B);
        const float* Vs = (const float*)(sm + AT_VOFF);

        // S = Q K^T  (m16 x n128, k64)
        float sc[16][4];
#pragma unroll
        for (int nt = 0; nt < 16; nt++) {
            sc[nt][0] = sc[nt][1] = sc[nt][2] = sc[nt][3] = 0.f;
            const float* kp = Ks + (nt * 8 + g) * KV_STRIDE;
#pragma unroll
            for (int kb = 0; kb < 8; kb++) {
                uint32_t bfr[2];
                bfr[0] = __float_as_uint(kp[kb * 8 + tq]);
                bfr[1] = __float_as_uint(kp[kb * 8 + tq + 4]);
                mma8(sc[nt], qa[kb], bfr);
            }
        }

        // prefetch next K into the other K buffer (safe: nobody reads it now)
        if (kc < qc) {
            attn_prefetch(sb + (uint32_t)(s ^ 1) * KV_STAGE_B,
                          g_k + head + (size_t)(kc + 1) * CHUNK_ * HD_, tid);
        }
        CP_COMMIT();

        // online softmax
        float smx_lo = -1e30f, smx_hi = -1e30f;
#pragma unroll
        for (int nt = 0; nt < 16; nt++) {
            smx_lo = fmaxf(smx_lo, fmaxf(sc[nt][0], sc[nt][1]));
            smx_hi = fmaxf(smx_hi, fmaxf(sc[nt][2], sc[nt][3]));
        }
        smx_lo = fmaxf(smx_lo, __shfl_xor_sync(0xffffffffu, smx_lo, 1));
        smx_lo = fmaxf(smx_lo, __shfl_xor_sync(0xffffffffu, smx_lo, 2));
        smx_hi = fmaxf(smx_hi, __shfl_xor_sync(0xffffffffu, smx_hi, 1));
        smx_hi = fmaxf(smx_hi, __shfl_xor_sync(0xffffffffu, smx_hi, 2));
        const float mn_lo = fmaxf(m_lo, smx_lo), mn_hi = fmaxf(m_hi, smx_hi);
        const float corr_lo = __expf(m_lo - mn_lo), corr_hi = __expf(m_hi - mn_hi);
        m_lo = mn_lo; m_hi = mn_hi;
        ls_lo *= corr_lo; ls_hi *= corr_hi;

        // p = exp(s - m); store tf32-rounded bits back into sc
#pragma unroll
        for (int nt = 0; nt < 16; nt++) {
            const float p0 = __expf(sc[nt][0] - mn_lo), p1 = __expf(sc[nt][1] - mn_lo);
            const float p2 = __expf(sc[nt][2] - mn_hi), p3 = __expf(sc[nt][3] - mn_hi);
            ls_lo += p0 + p1; ls_hi += p2 + p3;
            sc[nt][0] = __uint_as_float(f2tf(p0));
            sc[nt][1] = __uint_as_float(f2tf(p1));
            sc[nt][2] = __uint_as_float(f2tf(p2));
            sc[nt][3] = __uint_as_float(f2tf(p3));
        }

#pragma unroll
        for (int nv = 0; nv < 8; nv++) {
            o[nv][0] *= corr_lo; o[nv][1] *= corr_lo;
            o[nv][2] *= corr_hi; o[nv][3] *= corr_hi;
        }

        // O += P V  (m16 x n64, k128); P A-frags via intra-quad shuffles
#pragma unroll
        for (int kb = 0; kb < 16; kb++) {
            const float a0 = __shfl_sync(0xffffffffu, sc[kb][0], srcA);
            const float a1 = __shfl_sync(0xffffffffu, sc[kb][1], srcA);
            const float a2 = __shfl_sync(0xffffffffu, sc[kb][2], srcA);
            const float a3 = __shfl_sync(0xffffffffu, sc[kb][3], srcA);
            const float b0 = __shfl_sync(0xffffffffu, sc[kb][0], srcB);
            const float b1 = __shfl_sync(0xffffffffu, sc[kb][1], srcB);
            const float b2 = __shfl_sync(0xffffffffu, sc[kb][2], srcB);
            const float b3 = __shfl_sync(0xffffffffu, sc[kb][3], srcB);
            uint32_t pa[4];
            pa[0] = __float_as_uint(sel ? a1 : a0);   // row g,   col kb*8+tq
            pa[1] = __float_as_uint(sel ? a3 : a2);   // row g+8, col kb*8+tq
            pa[2] = __float_as_uint(sel ? b1 : b0);   // row g,   col kb*8+tq+4
            pa[3] = __float_as_uint(sel ? b3 : b2);   // row g+8, col kb*8+tq+4
#pragma unroll
            for (int nv = 0; nv < 8; nv++) {
                uint32_t vb[2];
                vb[0] = __float_as_uint(Vs[(kb * 8 + tq) * KV_STRIDE + nv * 8 + g]);
                vb[1] = __float_as_uint(Vs[(kb * 8 + tq + 4) * KV_STRIDE + nv * 8 + g]);
                mma8(o[nv], pa, vb);
            }
        }

        __syncthreads();   // all warps done reading V before overwrite
        if (kc < qc) {
            attn_prefetch(sb + AT_VOFF,
                          g_v + head + (size_t)(kc + 1) * CHUNK_ * HD_, tid);
        }
        CP_COMMIT();
        s ^= 1;
    }

    ls_lo += __shfl_xor_sync(0xffffffffu, ls_lo, 1);
    ls_lo += __shfl_xor_sync(0xffffffffu, ls_lo, 2);
    ls_hi += __shfl_xor_sync(0xffffffffu, ls_hi, 1);
    ls_hi += __shfl_xor_sync(0xffffffffu, ls_hi, 2);
    const float il = 1.f / ls_lo, ih = 1.f / ls_hi;

    // write ctx tf32-rounded (out-proj GEMM consumes it with no cvt)
    const int r0 = qc * CHUNK_ + m0 + g;
#pragma unroll
    for (int nv = 0; nv < 8; nv++) {
        const int col = h * HD_ + nv * 8 + 2 * tq;
        *(float2*)(ctx + ((size_t)b * L_ + r0) * D_ + col) =
            make_float2(f2tff(o[nv][0] * il), f2tff(o[nv][1] * il));
        *(float2*)(ctx + ((size_t)b * L_ + r0 + 8) * D_ + col) =
            make_float2(f2tff(o[nv][2] * ih), f2tff(o[nv][3] * ih));
    }
}

// ---------------------------------------------------------------------------
extern "C" void kernel_launch(void* const* d_in, const int* in_sizes, int n_in,
                              void* d_out, int out_size)
{
    const float* x    = (const float*)d_in[0];
    const float* Wqkv = (const float*)d_in[1];
    const float* bqkv = (const float*)d_in[2];
    const float* Wout = (const float*)d_in[3];
    const float* bout = (const float*)d_in[4];
    float* out = (float*)d_out;

    (void)in_sizes; (void)n_in; (void)out_size;

    cudaFuncSetAttribute(gemm_mma_kernel, cudaFuncAttributeMaxDynamicSharedMemorySize, GEMM_SMEM);
    cudaFuncSetAttribute(attn_mma_kernel, cudaFuncAttributeMaxDynamicSharedMemorySize, ATTN_SMEM);

    float *ctx_ptr, *xr, *wqkvr, *woutr;
    cudaGetSymbolAddress((void**)&ctx_ptr, g_ctx);
    cudaGetSymbolAddress((void**)&xr, g_xr);
    cudaGetSymbolAddress((void**)&wqkvr, g_wqkvr);
    cudaGetSymbolAddress((void**)&woutr, g_woutr);

    // 0. pre-round inputs to tf32 (removes all cvt from GEMM hot loops)
    {
        const int n1 = M_ROWS * D_ / 4, n2 = D_ * QKV_N / 4, n3 = D_ * D_ / 4;
        tf32_round_kernel<<<(n1 + 255) / 256, 256>>>((const float4*)x, (float4*)xr, n1);
        tf32_round_kernel<<<(n2 + 255) / 256, 256>>>((const float4*)Wqkv, (float4*)wqkvr, n2);
        tf32_round_kernel<<<(n3 + 255) / 256, 256>>>((const float4*)Wout, (float4*)woutr, n3);
    }
    // 1. QKV projection + scatter to [b,h,l,d] (tf32-rounded)
    {
        dim3 grid(QKV_N / 128, M_ROWS / 128);   // (24, 32)
        gemm_mma_kernel<<<grid, 256, GEMM_SMEM>>>(xr, wqkvr, bqkv, nullptr,
                                                  M_ROWS, QKV_N, D_, 1);
    }
    // 2. Block-causal attention -> g_ctx (tf32-rounded)
    {
        dim3 grid(L_ / CHUNK_, B_ * H_);        // (16, 32)
        attn_mma_kernel<<<grid, 256, ATTN_SMEM>>>(ctx_ptr);
    }
    // 3. Output projection -> d_out
    {
        dim3 grid(D_ / 128, M_ROWS / 128);      // (8, 32)
        gemm_mma_kernel<<<grid, 256, GEMM_SMEM>>>(ctx_ptr, woutr, bout, out,
                                                  M_ROWS, D_, D_, 0);
    }
}

// round 5
// speedup vs baseline: 4.2889x; 1.1774x over previous
#include <cuda_runtime.h>
#include <cstdint>

// Problem constants
#define B_      2
#define L_      2048
#define D_      1024
#define H_      16
#define HD_     64
#define CHUNK_  128
#define M_ROWS  (B_ * L_)          // 4096
#define QKV_N   (3 * D_)           // 3072

// Scratch (device globals — no allocation allowed)
__device__ __align__(16) float g_q[(size_t)B_ * H_ * L_ * HD_];     // [bh][l][perm(d)]
__device__ __align__(16) float g_k[(size_t)B_ * H_ * L_ * HD_];     // [bh][l][perm(d)]
__device__ __align__(16) float g_v[(size_t)B_ * H_ * HD_ * L_];     // [bh][d][perm-keys(l)]
__device__ __align__(16) float g_ctx[(size_t)B_ * L_ * D_];         // [m][perm(c)]
__device__ __align__(16) float g_xr[(size_t)M_ROWS * D_];           // [m][perm(k)]
__device__ __align__(16) float g_wqkvr[(size_t)QKV_N * D_];         // [n][perm(k)] (transposed)
__device__ __align__(16) float g_woutr[(size_t)D_ * D_];            // [n][perm(k)] (transposed)

// ===========================================================================
// Helpers
// ===========================================================================
__device__ __forceinline__ uint32_t smem_u32(const void* p) {
    uint32_t a;
    asm("{ .reg .u64 t; cvta.to.shared.u64 t, %1; cvt.u32.u64 %0, t; }" : "=r"(a) : "l"(p));
    return a;
}
__device__ __forceinline__ uint32_t f2tf(float x) {
    uint32_t r;
    asm("cvt.rna.tf32.f32 %0, %1;" : "=r"(r) : "f"(x));
    return r;
}
__device__ __forceinline__ float f2tff(float x) { return __uint_as_float(f2tf(x)); }

// K-dim permutation: within each 8-group, b -> ((b&3)<<1)|(b>>2)
// so that (k, k+4) land adjacent -> 64-bit fragment loads.
__device__ __forceinline__ int perm_idx(int i) {
    return (i & ~7) | ((i & 3) << 1) | ((i >> 2) & 1);
}

// m16n8k8 tf32 mma: D = A*B + D  (A row-major, B col-major)
__device__ __forceinline__ void mma8(float* c, const uint32_t* a, const uint32_t* b) {
    asm volatile(
        "mma.sync.aligned.m16n8k8.row.col.f32.tf32.tf32.f32 "
        "{%0,%1,%2,%3}, {%4,%5,%6,%7}, {%8,%9}, {%0,%1,%2,%3};"
        : "+f"(c[0]), "+f"(c[1]), "+f"(c[2]), "+f"(c[3])
        : "r"(a[0]), "r"(a[1]), "r"(a[2]), "r"(a[3]), "r"(b[0]), "r"(b[1]));
}

__device__ __forceinline__ void cp16(uint32_t dst, const void* src) {
    asm volatile("cp.async.cg.shared.global [%0], [%1], 16;" :: "r"(dst), "l"(src));
}
#define CP_COMMIT() asm volatile("cp.async.commit_group;" ::: "memory")
#define CP_WAIT0()  asm volatile("cp.async.wait_group 0;" ::: "memory")
#define CP_WAIT1()  asm volatile("cp.async.wait_group 1;" ::: "memory")

// ===========================================================================
// Prep kernels
// ===========================================================================
// x: round to tf32 + permute K-dim (groups of 8 contiguous)
__global__ __launch_bounds__(256) void roundperm_kernel(
    const float4* __restrict__ in, float4* __restrict__ out, int n8)
{
    const int i = blockIdx.x * blockDim.x + threadIdx.x;
    if (i < n8) {
        const float4 a = in[2 * i], b = in[2 * i + 1];
        out[2 * i]     = make_float4(f2tff(a.x), f2tff(b.x), f2tff(a.y), f2tff(b.y));
        out[2 * i + 1] = make_float4(f2tff(a.z), f2tff(b.z), f2tff(a.w), f2tff(b.w));
    }
}

// W[K][N] -> Wt[N][perm(K)] with tf32 rounding (tiled transpose)
__global__ __launch_bounds__(256) void transperm_kernel(
    const float* __restrict__ in, float* __restrict__ out, int K, int N)
{
    __shared__ float tile[32][33];
    const int k0 = blockIdx.y * 32, n0 = blockIdx.x * 32;
    const int tx = threadIdx.x, ty = threadIdx.y;    // 32 x 8
#pragma unroll
    for (int i = 0; i < 4; i++)
        tile[ty + 8 * i][tx] = in[(size_t)(k0 + ty + 8 * i) * N + n0 + tx];
    __syncthreads();
    const int kp = k0 + perm_idx(tx);
#pragma unroll
    for (int i = 0; i < 4; i++)
        out[(size_t)(n0 + ty + 8 * i) * K + kp] = f2tff(tile[tx][ty + 8 * i]);
}

// ===========================================================================
// tf32 mma GEMM: C[M,N] = A[M,K] @ W[K,N] + bias
// A: [M][perm(K)], Bt: [N][perm(K)] (pre-transposed+permuted, tf32-rounded).
// 128x128 CTA tile, BK=32, 256 thr (8 warps 2x4, warp tile 64x32), 2-stage.
// All fragment loads are LDS.64, conflict-free (stride 40 ≡ 8 mod 32).
// ===========================================================================
#define GS 40
#define GSTAGE_B (128 * GS * 4)    // 20480 bytes per stage per operand
#define G_BOFF   (2 * GSTAGE_B)
#define GEMM_SMEM (4 * GSTAGE_B)   // 81920 bytes

__device__ __forceinline__ void gemm_prefetch(
    uint32_t sb, int s, const float* A, const float* Bt,
    int K, int bm, int bn, int k0, int tid)
{
    const uint32_t a_st = sb + (uint32_t)s * GSTAGE_B;
    const uint32_t b_st = sb + G_BOFF + (uint32_t)s * GSTAGE_B;
#pragma unroll
    for (int i = 0; i < 4; i++) {
        const int idx = tid + i * 256;       // 0..1023
        const int r = idx >> 3, c = idx & 7;
        cp16(a_st + r * (GS * 4) + c * 16, A + (size_t)(bm + r) * K + k0 + c * 4);
    }
#pragma unroll
    for (int i = 0; i < 4; i++) {
        const int idx = tid + i * 256;
        const int r = idx >> 3, c = idx & 7;
        cp16(b_st + r * (GS * 4) + c * 16, Bt + (size_t)(bn + r) * K + k0 + c * 4);
    }
}

__global__ __launch_bounds__(256, 2) void gemm_mma_kernel(
    const float* __restrict__ A, const float* __restrict__ Bt,
    const float* __restrict__ bias, float* __restrict__ C,
    int M, int N, int K, int qkv_mode)
{
    extern __shared__ __align__(16) char sm[];
    const uint32_t sb = smem_u32(sm);
    const int tid = threadIdx.x, wid = tid >> 5, lane = tid & 31;
    const int g = lane >> 2, tq = lane & 3;
    const int bm = blockIdx.y * 128, bn = blockIdx.x * 128;
    const int wm = (wid >> 2) * 64, wn = (wid & 3) * 32;

    float c[4][4][4];
#pragma unroll
    for (int mt = 0; mt < 4; mt++)
#pragma unroll
        for (int nt = 0; nt < 4; nt++)
#pragma unroll
            for (int i = 0; i < 4; i++) c[mt][nt][i] = 0.f;

    const int KT = K >> 5;
    gemm_prefetch(sb, 0, A, Bt, K, bm, bn, 0, tid);  CP_COMMIT();
    gemm_prefetch(sb, 1, A, Bt, K, bm, bn, 32, tid); CP_COMMIT();

    for (int t = 0; t < KT; t++) {
        CP_WAIT1();
        __syncthreads();
        const int s = t & 1;
        {
            const float* As = (const float*)(sm + (size_t)s * GSTAGE_B);
            const float* Bs = (const float*)(sm + G_BOFF + (size_t)s * GSTAGE_B);
#pragma unroll
            for (int kb = 0; kb < 4; kb++) {
                uint32_t af[4][4], bf[4][2];
#pragma unroll
                for (int mt = 0; mt < 4; mt++) {
                    const float2 lo = *(const float2*)(As + (wm + mt * 16 + g) * GS + kb * 8 + tq * 2);
                    const float2 hi = *(const float2*)(As + (wm + mt * 16 + g + 8) * GS + kb * 8 + tq * 2);
                    af[mt][0] = __float_as_uint(lo.x);
                    af[mt][1] = __float_as_uint(hi.x);
                    af[mt][2] = __float_as_uint(lo.y);
                    af[mt][3] = __float_as_uint(hi.y);
                }
#pragma unroll
                for (int nt = 0; nt < 4; nt++) {
                    const float2 bb = *(const float2*)(Bs + (wn + nt * 8 + g) * GS + kb * 8 + tq * 2);
                    bf[nt][0] = __float_as_uint(bb.x);
                    bf[nt][1] = __float_as_uint(bb.y);
                }
#pragma unroll
                for (int mt = 0; mt < 4; mt++)
#pragma unroll
                    for (int nt = 0; nt < 4; nt++)
                        mma8(c[mt][nt], af[mt], bf[nt]);
            }
        }
        __syncthreads();
        if (t + 2 < KT)
            gemm_prefetch(sb, s, A, Bt, K, bm, bn, (t + 2) * 32, tid);
        CP_COMMIT();
    }

    // Epilogue: c0:(g,2tq) c1:(g,2tq+1) c2:(g+8,2tq) c3:(g+8,2tq+1)
#pragma unroll
    for (int mt = 0; mt < 4; mt++) {
#pragma unroll
        for (int nt = 0; nt < 4; nt++) {
            const int col = bn + wn + nt * 8 + 2 * tq;
            const float b0 = bias[col], b1 = bias[col + 1];
            const int r0 = bm + wm + mt * 16 + g;
            const int r1 = r0 + 8;
            float v00 = c[mt][nt][0] + b0, v01 = c[mt][nt][1] + b1;
            float v10 = c[mt][nt][2] + b0, v11 = c[mt][nt][3] + b1;
            if (qkv_mode) {
                v00 = f2tff(v00); v01 = f2tff(v01);
                v10 = f2tff(v10); v11 = f2tff(v11);
                const int which = col >> 10;
                const int h  = (col >> 6) & 15;
                const int dd = col & 63;
                const int bh0 = (r0 >> 11) * H_ + h, l0 = r0 & 2047;
                const int bh1 = (r1 >> 11) * H_ + h, l1 = r1 & 2047;
                if (which == 2) {
                    // V: [bh][d][perm-keys(l)]
                    const int p0 = perm_idx(l0), p1 = perm_idx(l1);
                    g_v[((size_t)bh0 * HD_ + dd) * L_ + p0]     = v00;
                    g_v[((size_t)bh0 * HD_ + dd + 1) * L_ + p0] = v01;
                    g_v[((size_t)bh1 * HD_ + dd) * L_ + p1]     = v10;
                    g_v[((size_t)bh1 * HD_ + dd + 1) * L_ + p1] = v11;
                } else {
                    float* tgt = (which == 0) ? g_q : g_k;
                    const int pd0 = perm_idx(dd), pd1 = perm_idx(dd + 1);
                    float* d0 = tgt + ((size_t)bh0 * L_ + l0) * HD_;
                    float* d1 = tgt + ((size_t)bh1 * L_ + l1) * HD_;
                    d0[pd0] = v00; d0[pd1] = v01;
                    d1[pd0] = v10; d1[pd1] = v11;
                }
            } else {
                *(float2*)(C + (size_t)r0 * N + col) = make_float2(v00, v01);
                *(float2*)(C + (size_t)r1 * N + col) = make_float2(v10, v11);
            }
        }
    }
}

// ===========================================================================
// Block-causal flash attention on mma.sync tf32.
// K smem [key][72] (d-permuted), V smem [d][136] (key-permuted) -> all frag
// loads LDS.64 conflict-free. K double-buffered, V single-buffered. 106 KB.
// ===========================================================================
#define KS_ 72
#define VS_ 136
#define K_STAGE_B (128 * KS_ * 4)            // 36864
#define AT_VOFF   (2 * K_STAGE_B)            // 73728
#define ATTN_SMEM (AT_VOFF + HD_ * VS_ * 4)  // 108544

__device__ __forceinline__ void attn_prefetch_k(uint32_t dst, const float* src, int tid)
{
#pragma unroll
    for (int i = 0; i < 8; i++) {
        const int idx = tid + i * 256;        // 0..2047
        const int r = idx >> 4, c = idx & 15;
        cp16(dst + r * (KS_ * 4) + c * 16, src + r * 64 + c * 4);
    }
}
__device__ __forceinline__ void attn_prefetch_v(uint32_t dst, const float* src, int tid)
{
#pragma unroll
    for (int i = 0; i < 8; i++) {
        const int idx = tid + i * 256;        // 0..2047
        const int r = idx >> 5, c = idx & 31; // 64 rows x 32 chunks
        cp16(dst + r * (VS_ * 4) + c * 16, src + (size_t)r * L_ + c * 4);
    }
}

__global__ __launch_bounds__(256, 2) void attn_mma_kernel(float* __restrict__ ctx)
{
    extern __shared__ __align__(16) char sm[];
    const uint32_t sb = smem_u32(sm);
    const int tid = threadIdx.x, wid = tid >> 5, lane = tid & 31;
    const int g = lane >> 2, tq = lane & 3;
    const int qc = 15 - (int)blockIdx.x;
    const int bh = blockIdx.y, b = bh >> 4, h = bh & 15;
    const size_t head  = (size_t)bh * L_ * HD_;
    const int m0 = wid * 16;

    // shuffle-transpose constants
    const int sel  = tq & 1;
    const int srcA = (lane & ~3) | (tq >> 1);
    const int srcB = srcA + 2;

    // Q fragments (tf32-rounded, d-permuted in gmem); fold in 1/8
    uint32_t qa[8][4];
    {
        const float* qb = g_q + head + (size_t)(qc * CHUNK_ + m0) * HD_;
#pragma unroll
        for (int kb = 0; kb < 8; kb++) {
            const float2 lo = *(const float2*)(qb + g * 64 + kb * 8 + tq * 2);
            const float2 hi = *(const float2*)(qb + (g + 8) * 64 + kb * 8 + tq * 2);
            qa[kb][0] = __float_as_uint(lo.x * 0.125f);
            qa[kb][1] = __float_as_uint(hi.x * 0.125f);
            qa[kb][2] = __float_as_uint(lo.y * 0.125f);
            qa[kb][3] = __float_as_uint(hi.y * 0.125f);
        }
    }

    float o[8][4];
#pragma unroll
    for (int nv = 0; nv < 8; nv++)
#pragma unroll
        for (int i = 0; i < 4; i++) o[nv][i] = 0.f;
    float m_lo = -1e30f, m_hi = -1e30f, ls_lo = 0.f, ls_hi = 0.f;

    // prologue: K(0) -> Kbuf0, V(0) -> Vbuf
    attn_prefetch_k(sb, g_k + head, tid);
    attn_prefetch_v(sb + AT_VOFF, g_v + head, tid);
    CP_COMMIT();

    int s = 0;
    for (int kc = 0; kc <= qc; kc++) {
        CP_WAIT0();
        __syncthreads();
        const float* Ks = (const float*)(sm + (size_t)s * K_STAGE_B);
        const float* Vs = (const float*)(sm + AT_VOFF);

        // S = Q K^T  (m16 x n128, k64)
        float sc[16][4];
#pragma unroll
        for (int nt = 0; nt < 16; nt++) {
            sc[nt][0] = sc[nt][1] = sc[nt][2] = sc[nt][3] = 0.f;
            const float* kp = Ks + (nt * 8 + g) * KS_;
#pragma unroll
            for (int kb = 0; kb < 8; kb++) {
                const float2 bb = *(const float2*)(kp + kb * 8 + tq * 2);
                uint32_t bfr[2];
                bfr[0] = __float_as_uint(bb.x);
                bfr[1] = __float_as_uint(bb.y);
                mma8(sc[nt], qa[kb], bfr);
            }
        }

        // prefetch next K into the other K buffer
        if (kc < qc)
            attn_prefetch_k(sb + (uint32_t)(s ^ 1) * K_STAGE_B,
                            g_k + head + (size_t)(kc + 1) * CHUNK_ * HD_, tid);
        CP_COMMIT();

        // online softmax
        float smx_lo = -1e30f, smx_hi = -1e30f;
#pragma unroll
        for (int nt = 0; nt < 16; nt++) {
            smx_lo = fmaxf(smx_lo, fmaxf(sc[nt][0], sc[nt][1]));
            smx_hi = fmaxf(smx_hi, fmaxf(sc[nt][2], sc[nt][3]));
        }
        smx_lo = fmaxf(smx_lo, __shfl_xor_sync(0xffffffffu, smx_lo, 1));
        smx_lo = fmaxf(smx_lo, __shfl_xor_sync(0xffffffffu, smx_lo, 2));
        smx_hi = fmaxf(smx_hi, __shfl_xor_sync(0xffffffffu, smx_hi, 1));
        smx_hi = fmaxf(smx_hi, __shfl_xor_sync(0xffffffffu, smx_hi, 2));
        const float mn_lo = fmaxf(m_lo, smx_lo), mn_hi = fmaxf(m_hi, smx_hi);
        const float corr_lo = __expf(m_lo - mn_lo), corr_hi = __expf(m_hi - mn_hi);
        m_lo = mn_lo; m_hi = mn_hi;
        ls_lo *= corr_lo; ls_hi *= corr_hi;

#pragma unroll
        for (int nt = 0; nt < 16; nt++) {
            const float p0 = __expf(sc[nt][0] - mn_lo), p1 = __expf(sc[nt][1] - mn_lo);
            const float p2 = __expf(sc[nt][2] - mn_hi), p3 = __expf(sc[nt][3] - mn_hi);
            ls_lo += p0 + p1; ls_hi += p2 + p3;
            sc[nt][0] = __uint_as_float(f2tf(p0));
            sc[nt][1] = __uint_as_float(f2tf(p1));
            sc[nt][2] = __uint_as_float(f2tf(p2));
            sc[nt][3] = __uint_as_float(f2tf(p3));
        }

#pragma unroll
        for (int nv = 0; nv < 8; nv++) {
            o[nv][0] *= corr_lo; o[nv][1] *= corr_lo;
            o[nv][2] *= corr_hi; o[nv][3] *= corr_hi;
        }

        // O += P V  (m16 x n64, k128); P A-frags via intra-quad shuffles
#pragma unroll
        for (int kb = 0; kb < 16; kb++) {
            const float a0 = __shfl_sync(0xffffffffu, sc[kb][0], srcA);
            const float a1 = __shfl_sync(0xffffffffu, sc[kb][1], srcA);
            const float a2 = __shfl_sync(0xffffffffu, sc[kb][2], srcA);
            const float a3 = __shfl_sync(0xffffffffu, sc[kb][3], srcA);
            const float b0 = __shfl_sync(0xffffffffu, sc[kb][0], srcB);
            const float b1 = __shfl_sync(0xffffffffu, sc[kb][1], srcB);
            const float b2 = __shfl_sync(0xffffffffu, sc[kb][2], srcB);
            const float b3 = __shfl_sync(0xffffffffu, sc[kb][3], srcB);
            uint32_t pa[4];
            pa[0] = __float_as_uint(sel ? a1 : a0);
            pa[1] = __float_as_uint(sel ? a3 : a2);
            pa[2] = __float_as_uint(sel ? b1 : b0);
            pa[3] = __float_as_uint(sel ? b3 : b2);
#pragma unroll
            for (int nv = 0; nv < 8; nv++) {
                const float2 vv = *(const float2*)(Vs + (nv * 8 + g) * VS_ + kb * 8 + tq * 2);
                uint32_t vb[2];
                vb[0] = __float_as_uint(vv.x);
                vb[1] = __float_as_uint(vv.y);
                mma8(o[nv], pa, vb);
            }
        }

        __syncthreads();   // all warps done reading V before overwrite
        if (kc < qc)
            attn_prefetch_v(sb + AT_VOFF,
                            g_v + head + (size_t)(kc + 1) * CHUNK_, tid);
        CP_COMMIT();
        s ^= 1;
    }

    ls_lo += __shfl_xor_sync(0xffffffffu, ls_lo, 1);
    ls_lo += __shfl_xor_sync(0xffffffffu, ls_lo, 2);
    ls_hi += __shfl_xor_sync(0xffffffffu, ls_hi, 1);
    ls_hi += __shfl_xor_sync(0xffffffffu, ls_hi, 2);
    const float il = 1.f / ls_lo, ih = 1.f / ls_hi;

    // write ctx tf32-rounded, K-permuted for the out-proj GEMM
    const int r0 = qc * CHUNK_ + m0 + g;
#pragma unroll
    for (int nv = 0; nv < 8; nv++) {
        const int col = h * HD_ + nv * 8 + 2 * tq;
        const int p0 = perm_idx(col), p1 = perm_idx(col + 1);
        float* c0 = ctx + ((size_t)b * L_ + r0) * D_;
        float* c1 = ctx + ((size_t)b * L_ + r0 + 8) * D_;
        c0[p0] = f2tff(o[nv][0] * il); c0[p1] = f2tff(o[nv][1] * il);
        c1[p0] = f2tff(o[nv][2] * ih); c1[p1] = f2tff(o[nv][3] * ih);
    }
}

// ---------------------------------------------------------------------------
extern "C" void kernel_launch(void* const* d_in, const int* in_sizes, int n_in,
                              void* d_out, int out_size)
{
    const float* x    = (const float*)d_in[0];
    const float* Wqkv = (const float*)d_in[1];
    const float* bqkv = (const float*)d_in[2];
    const float* Wout = (const float*)d_in[3];
    const float* bout = (const float*)d_in[4];
    float* out = (float*)d_out;

    (void)in_sizes; (void)n_in; (void)out_size;

    cudaFuncSetAttribute(gemm_mma_kernel, cudaFuncAttributeMaxDynamicSharedMemorySize, GEMM_SMEM);
    cudaFuncSetAttribute(attn_mma_kernel, cudaFuncAttributeMaxDynamicSharedMemorySize, ATTN_SMEM);

    float *ctx_ptr, *xr, *wqkvr, *woutr;
    cudaGetSymbolAddress((void**)&ctx_ptr, g_ctx);
    cudaGetSymbolAddress((void**)&xr, g_xr);
    cudaGetSymbolAddress((void**)&wqkvr, g_wqkvr);
    cudaGetSymbolAddress((void**)&woutr, g_woutr);

    // 0. prep: round+permute x; transpose+round+permute weights
    {
        const int n8 = M_ROWS * D_ / 8;
        roundperm_kernel<<<(n8 + 255) / 256, 256>>>((const float4*)x, (float4*)xr, n8);
        dim3 blk(32, 8);
        transperm_kernel<<<dim3(QKV_N / 32, D_ / 32), blk>>>(Wqkv, wqkvr, D_, QKV_N);
        transperm_kernel<<<dim3(D_ / 32, D_ / 32), blk>>>(Wout, woutr, D_, D_);
    }
    // 1. QKV projection + scatter to q/k [bh][l][perm(d)], v [bh][d][perm(l)]
    {
        dim3 grid(QKV_N / 128, M_ROWS / 128);   // (24, 32)
        gemm_mma_kernel<<<grid, 256, GEMM_SMEM>>>(xr, wqkvr, bqkv, nullptr,
                                                  M_ROWS, QKV_N, D_, 1);
    }
    // 2. Block-causal attention -> g_ctx (permuted, tf32-rounded)
    {
        dim3 grid(L_ / CHUNK_, B_ * H_);        // (16, 32)
        attn_mma_kernel<<<grid, 256, ATTN_SMEM>>>(ctx_ptr);
    }
    // 3. Output projection -> d_out
    {
        dim3 grid(D_ / 128, M_ROWS / 128);      // (8, 32)
        gemm_mma_kernel<<<grid, 256, GEMM_SMEM>>>(ctx_ptr, woutr, bout, out,
                                                  M_ROWS, D_, D_, 0);
    }
}

// round 6
// speedup vs baseline: 4.5735x; 1.0664x over previous
#include <cuda_runtime.h>
#include <cstdint>

// Problem constants
#define B_      2
#define L_      2048
#define D_      1024
#define H_      16
#define HD_     64
#define CHUNK_  128
#define M_ROWS  (B_ * L_)          // 4096
#define QKV_N   (3 * D_)           // 3072

// Scratch (device globals — no allocation allowed)
__device__ __align__(16) float g_q[(size_t)B_ * H_ * L_ * HD_];     // [bh][l][perm(d)]
__device__ __align__(16) float g_k[(size_t)B_ * H_ * L_ * HD_];     // [bh][l][perm(d)]
__device__ __align__(16) float g_v[(size_t)B_ * H_ * HD_ * L_];     // [bh][d][l]  (UNpermuted keys)
__device__ __align__(16) float g_ctx[(size_t)B_ * L_ * D_];         // [m][perm(c)]
__device__ __align__(16) float g_xr[(size_t)M_ROWS * D_];           // [m][perm(k)]
__device__ __align__(16) float g_wqkvr[(size_t)QKV_N * D_];         // [n][perm(k)] (transposed)
__device__ __align__(16) float g_woutr[(size_t)D_ * D_];            // [n][perm(k)] (transposed)

// ===========================================================================
// Helpers
// ===========================================================================
__device__ __forceinline__ uint32_t smem_u32(const void* p) {
    uint32_t a;
    asm("{ .reg .u64 t; cvta.to.shared.u64 t, %1; cvt.u32.u64 %0, t; }" : "=r"(a) : "l"(p));
    return a;
}
__device__ __forceinline__ uint32_t f2tf(float x) {
    uint32_t r;
    asm("cvt.rna.tf32.f32 %0, %1;" : "=r"(r) : "f"(x));
    return r;
}
__device__ __forceinline__ float f2tff(float x) { return __uint_as_float(f2tf(x)); }

// K-dim permutation: within each 8-group, b -> ((b&3)<<1)|(b>>2)
// so that fragment pairs (k, k+4) land adjacent -> 64-bit loads.
__device__ __forceinline__ int perm_idx(int i) {
    return (i & ~7) | ((i & 3) << 1) | ((i >> 2) & 1);
}

// m16n8k8 tf32 mma: D = A*B + D  (A row-major, B col-major)
__device__ __forceinline__ void mma8(float* c, const uint32_t* a, const uint32_t* b) {
    asm volatile(
        "mma.sync.aligned.m16n8k8.row.col.f32.tf32.tf32.f32 "
        "{%0,%1,%2,%3}, {%4,%5,%6,%7}, {%8,%9}, {%0,%1,%2,%3};"
        : "+f"(c[0]), "+f"(c[1]), "+f"(c[2]), "+f"(c[3])
        : "r"(a[0]), "r"(a[1]), "r"(a[2]), "r"(a[3]), "r"(b[0]), "r"(b[1]));
}

__device__ __forceinline__ void cp16(uint32_t dst, const void* src) {
    asm volatile("cp.async.cg.shared.global [%0], [%1], 16;" :: "r"(dst), "l"(src));
}
#define CP_COMMIT() asm volatile("cp.async.commit_group;" ::: "memory")
#define CP_WAIT0()  asm volatile("cp.async.wait_group 0;" ::: "memory")
#define CP_WAIT1()  asm volatile("cp.async.wait_group 1;" ::: "memory")

// ===========================================================================
// Prep kernels
// ===========================================================================
__global__ __launch_bounds__(256) void roundperm_kernel(
    const float4* __restrict__ in, float4* __restrict__ out, int n8)
{
    const int i = blockIdx.x * blockDim.x + threadIdx.x;
    if (i < n8) {
        const float4 a = in[2 * i], b = in[2 * i + 1];
        out[2 * i]     = make_float4(f2tff(a.x), f2tff(b.x), f2tff(a.y), f2tff(b.y));
        out[2 * i + 1] = make_float4(f2tff(a.z), f2tff(b.z), f2tff(a.w), f2tff(b.w));
    }
}

// W[K][N] -> Wt[N][perm(K)] with tf32 rounding (tiled transpose)
__global__ __launch_bounds__(256) void transperm_kernel(
    const float* __restrict__ in, float* __restrict__ out, int K, int N)
{
    __shared__ float tile[32][33];
    const int k0 = blockIdx.y * 32, n0 = blockIdx.x * 32;
    const int tx = threadIdx.x, ty = threadIdx.y;    // 32 x 8
#pragma unroll
    for (int i = 0; i < 4; i++)
        tile[ty + 8 * i][tx] = in[(size_t)(k0 + ty + 8 * i) * N + n0 + tx];
    __syncthreads();
    const int kp = k0 + perm_idx(tx);
#pragma unroll
    for (int i = 0; i < 4; i++)
        out[(size_t)(n0 + ty + 8 * i) * K + kp] = f2tff(tile[tx][ty + 8 * i]);
}

// ===========================================================================
// tf32 mma GEMM: C[M,N] = A[M,K] @ W[K,N] + bias
// A: [M][perm(K)], Bt: [N][perm(K)] (pre-transposed+permuted, tf32-rounded).
// 128x128 CTA tile, BK=32, 256 thr (8 warps 2x4, warp tile 64x32), 2-stage.
// ===========================================================================
#define GS 40
#define GSTAGE_B (128 * GS * 4)
#define G_BOFF   (2 * GSTAGE_B)
#define GEMM_SMEM (4 * GSTAGE_B)   // 81920 bytes

__device__ __forceinline__ void gemm_prefetch(
    uint32_t sb, int s, const float* A, const float* Bt,
    int K, int bm, int bn, int k0, int tid)
{
    const uint32_t a_st = sb + (uint32_t)s * GSTAGE_B;
    const uint32_t b_st = sb + G_BOFF + (uint32_t)s * GSTAGE_B;
#pragma unroll
    for (int i = 0; i < 4; i++) {
        const int idx = tid + i * 256;
        const int r = idx >> 3, c = idx & 7;
        cp16(a_st + r * (GS * 4) + c * 16, A + (size_t)(bm + r) * K + k0 + c * 4);
    }
#pragma unroll
    for (int i = 0; i < 4; i++) {
        const int idx = tid + i * 256;
        const int r = idx >> 3, c = idx & 7;
        cp16(b_st + r * (GS * 4) + c * 16, Bt + (size_t)(bn + r) * K + k0 + c * 4);
    }
}

__global__ __launch_bounds__(256, 2) void gemm_mma_kernel(
    const float* __restrict__ A, const float* __restrict__ Bt,
    const float* __restrict__ bias, float* __restrict__ C,
    int M, int N, int K, int qkv_mode)
{
    extern __shared__ __align__(16) char sm[];
    const uint32_t sb = smem_u32(sm);
    const int tid = threadIdx.x, wid = tid >> 5, lane = tid & 31;
    const int g = lane >> 2, tq = lane & 3;
    const int bm = blockIdx.y * 128, bn = blockIdx.x * 128;
    const int wm = (wid >> 2) * 64, wn = (wid & 3) * 32;

    float c[4][4][4];
#pragma unroll
    for (int mt = 0; mt < 4; mt++)
#pragma unroll
        for (int nt = 0; nt < 4; nt++)
#pragma unroll
            for (int i = 0; i < 4; i++) c[mt][nt][i] = 0.f;

    const int KT = K >> 5;
    gemm_prefetch(sb, 0, A, Bt, K, bm, bn, 0, tid);  CP_COMMIT();
    gemm_prefetch(sb, 1, A, Bt, K, bm, bn, 32, tid); CP_COMMIT();

    for (int t = 0; t < KT; t++) {
        CP_WAIT1();
        __syncthreads();
        const int s = t & 1;
        {
            const float* As = (const float*)(sm + (size_t)s * GSTAGE_B);
            const float* Bs = (const float*)(sm + G_BOFF + (size_t)s * GSTAGE_B);
#pragma unroll
            for (int kb = 0; kb < 4; kb++) {
                uint32_t af[4][4], bf[4][2];
#pragma unroll
                for (int mt = 0; mt < 4; mt++) {
                    const float2 lo = *(const float2*)(As + (wm + mt * 16 + g) * GS + kb * 8 + tq * 2);
                    const float2 hi = *(const float2*)(As + (wm + mt * 16 + g + 8) * GS + kb * 8 + tq * 2);
                    af[mt][0] = __float_as_uint(lo.x);
                    af[mt][1] = __float_as_uint(hi.x);
                    af[mt][2] = __float_as_uint(lo.y);
                    af[mt][3] = __float_as_uint(hi.y);
                }
#pragma unroll
                for (int nt = 0; nt < 4; nt++) {
                    const float2 bb = *(const float2*)(Bs + (wn + nt * 8 + g) * GS + kb * 8 + tq * 2);
                    bf[nt][0] = __float_as_uint(bb.x);
                    bf[nt][1] = __float_as_uint(bb.y);
                }
#pragma unroll
                for (int mt = 0; mt < 4; mt++)
#pragma unroll
                    for (int nt = 0; nt < 4; nt++)
                        mma8(c[mt][nt], af[mt], bf[nt]);
            }
        }
        __syncthreads();
        if (t + 2 < KT)
            gemm_prefetch(sb, s, A, Bt, K, bm, bn, (t + 2) * 32, tid);
        CP_COMMIT();
    }

    // Epilogue: c0:(g,2tq) c1:(g,2tq+1) c2:(g+8,2tq) c3:(g+8,2tq+1)
#pragma unroll
    for (int mt = 0; mt < 4; mt++) {
#pragma unroll
        for (int nt = 0; nt < 4; nt++) {
            const int col = bn + wn + nt * 8 + 2 * tq;
            const float b0 = bias[col], b1 = bias[col + 1];
            const int r0 = bm + wm + mt * 16 + g;
            const int r1 = r0 + 8;
            float v00 = c[mt][nt][0] + b0, v01 = c[mt][nt][1] + b1;
            float v10 = c[mt][nt][2] + b0, v11 = c[mt][nt][3] + b1;
            if (qkv_mode) {
                v00 = f2tff(v00); v01 = f2tff(v01);
                v10 = f2tff(v10); v11 = f2tff(v11);
                const int which = col >> 10;
                const int h  = (col >> 6) & 15;
                const int dd = col & 63;
                const int bh0 = (r0 >> 11) * H_ + h, l0 = r0 & 2047;
                const int bh1 = (r1 >> 11) * H_ + h, l1 = r1 & 2047;
                if (which == 2) {
                    // V: [bh][d][l]  (keys UNpermuted — C-frag relabeling trick)
                    g_v[((size_t)bh0 * HD_ + dd) * L_ + l0]     = v00;
                    g_v[((size_t)bh0 * HD_ + dd + 1) * L_ + l0] = v01;
                    g_v[((size_t)bh1 * HD_ + dd) * L_ + l1]     = v10;
                    g_v[((size_t)bh1 * HD_ + dd + 1) * L_ + l1] = v11;
                } else {
                    float* tgt = (which == 0) ? g_q : g_k;
                    const int pd0 = perm_idx(dd), pd1 = perm_idx(dd + 1);
                    float* d0 = tgt + ((size_t)bh0 * L_ + l0) * HD_;
                    float* d1 = tgt + ((size_t)bh1 * L_ + l1) * HD_;
                    d0[pd0] = v00; d0[pd1] = v01;
                    d1[pd0] = v10; d1[pd1] = v11;
                }
            } else {
                *(float2*)(C + (size_t)r0 * N + col) = make_float2(v00, v01);
                *(float2*)(C + (size_t)r1 * N + col) = make_float2(v10, v11);
            }
        }
    }
}

// ===========================================================================
// Block-causal flash attention on mma.sync tf32.
// S C-fragment is reused DIRECTLY as the PV A-fragment: the P columns a
// C-frag thread holds (2tq, 2tq+1) are exactly the keys the float2 V B-frag
// load supplies when V is stored key-unpermuted. Zero shuffles.
// ===========================================================================
#define KS_ 72
#define VS_ 136
#define K_STAGE_B (128 * KS_ * 4)            // 36864
#define AT_VOFF   (2 * K_STAGE_B)            // 73728
#define ATTN_SMEM (AT_VOFF + HD_ * VS_ * 4)  // 108544

__device__ __forceinline__ void attn_prefetch_k(uint32_t dst, const float* src, int tid)
{
#pragma unroll
    for (int i = 0; i < 8; i++) {
        const int idx = tid + i * 256;
        const int r = idx >> 4, c = idx & 15;
        cp16(dst + r * (KS_ * 4) + c * 16, src + r * 64 + c * 4);
    }
}
__device__ __forceinline__ void attn_prefetch_v(uint32_t dst, const float* src, int tid)
{
#pragma unroll
    for (int i = 0; i < 8; i++) {
        const int idx = tid + i * 256;
        const int r = idx >> 5, c = idx & 31; // 64 d-rows x 32 16B-chunks
        cp16(dst + r * (VS_ * 4) + c * 16, src + (size_t)r * L_ + c * 4);
    }
}

__global__ __launch_bounds__(256, 2) void attn_mma_kernel(float* __restrict__ ctx)
{
    extern __shared__ __align__(16) char sm[];
    const uint32_t sb = smem_u32(sm);
    const int tid = threadIdx.x, wid = tid >> 5, lane = tid & 31;
    const int g = lane >> 2, tq = lane & 3;
    const int qc = 15 - (int)blockIdx.x;
    const int bh = blockIdx.y, b = bh >> 4, h = bh & 15;
    const size_t head = (size_t)bh * L_ * HD_;
    const int m0 = wid * 16;

    // Q fragments (tf32-rounded, d-permuted in gmem); fold in 1/8
    uint32_t qa[8][4];
    {
        const float* qb = g_q + head + (size_t)(qc * CHUNK_ + m0) * HD_;
#pragma unroll
        for (int kb = 0; kb < 8; kb++) {
            const float2 lo = *(const float2*)(qb + g * 64 + kb * 8 + tq * 2);
            const float2 hi = *(const float2*)(qb + (g + 8) * 64 + kb * 8 + tq * 2);
            qa[kb][0] = __float_as_uint(lo.x * 0.125f);
            qa[kb][1] = __float_as_uint(hi.x * 0.125f);
            qa[kb][2] = __float_as_uint(lo.y * 0.125f);
            qa[kb][3] = __float_as_uint(hi.y * 0.125f);
        }
    }

    float o[8][4];
#pragma unroll
    for (int nv = 0; nv < 8; nv++)
#pragma unroll
        for (int i = 0; i < 4; i++) o[nv][i] = 0.f;
    float m_lo = -1e30f, m_hi = -1e30f, ls_lo = 0.f, ls_hi = 0.f;

    // prologue: K(0) -> Kbuf0, V(0) -> Vbuf
    attn_prefetch_k(sb, g_k + head, tid);
    attn_prefetch_v(sb + AT_VOFF, g_v + head, tid);
    CP_COMMIT();

    int s = 0;
    for (int kc = 0; kc <= qc; kc++) {
        CP_WAIT0();
        __syncthreads();
        const float* Ks = (const float*)(sm + (size_t)s * K_STAGE_B);
        const float* Vs = (const float*)(sm + AT_VOFF);

        // S = Q K^T  (m16 x n128, k64)
        float sc[16][4];
#pragma unroll
        for (int nt = 0; nt < 16; nt++) {
            sc[nt][0] = sc[nt][1] = sc[nt][2] = sc[nt][3] = 0.f;
            const float* kp = Ks + (nt * 8 + g) * KS_;
#pragma unroll
            for (int kb = 0; kb < 8; kb++) {
                const float2 bb = *(const float2*)(kp + kb * 8 + tq * 2);
                uint32_t bfr[2];
                bfr[0] = __float_as_uint(bb.x);
                bfr[1] = __float_as_uint(bb.y);
                mma8(sc[nt], qa[kb], bfr);
            }
        }

        // prefetch next K into the other K buffer
        if (kc < qc)
            attn_prefetch_k(sb + (uint32_t)(s ^ 1) * K_STAGE_B,
                            g_k + head + (size_t)(kc + 1) * CHUNK_ * HD_, tid);
        CP_COMMIT();

        // online softmax
        float smx_lo = -1e30f, smx_hi = -1e30f;
#pragma unroll
        for (int nt = 0; nt < 16; nt++) {
            smx_lo = fmaxf(smx_lo, fmaxf(sc[nt][0], sc[nt][1]));
            smx_hi = fmaxf(smx_hi, fmaxf(sc[nt][2], sc[nt][3]));
        }
        smx_lo = fmaxf(smx_lo, __shfl_xor_sync(0xffffffffu, smx_lo, 1));
        smx_lo = fmaxf(smx_lo, __shfl_xor_sync(0xffffffffu, smx_lo, 2));
        smx_hi = fmaxf(smx_hi, __shfl_xor_sync(0xffffffffu, smx_hi, 1));
        smx_hi = fmaxf(smx_hi, __shfl_xor_sync(0xffffffffu, smx_hi, 2));
        const float mn_lo = fmaxf(m_lo, smx_lo), mn_hi = fmaxf(m_hi, smx_hi);
        const float corr_lo = __expf(m_lo - mn_lo), corr_hi = __expf(m_hi - mn_hi);
        m_lo = mn_lo; m_hi = mn_hi;
        ls_lo *= corr_lo; ls_hi *= corr_hi;

        // p = exp(s - m), tf32-rounded in place: sc becomes the PV A-fragment
#pragma unroll
        for (int nt = 0; nt < 16; nt++) {
            const float p0 = __expf(sc[nt][0] - mn_lo), p1 = __expf(sc[nt][1] - mn_lo);
            const float p2 = __expf(sc[nt][2] - mn_hi), p3 = __expf(sc[nt][3] - mn_hi);
            ls_lo += p0 + p1; ls_hi += p2 + p3;
            sc[nt][0] = __uint_as_float(f2tf(p0));
            sc[nt][1] = __uint_as_float(f2tf(p1));
            sc[nt][2] = __uint_as_float(f2tf(p2));
            sc[nt][3] = __uint_as_float(f2tf(p3));
        }

#pragma unroll
        for (int nv = 0; nv < 8; nv++) {
            o[nv][0] *= corr_lo; o[nv][1] *= corr_lo;
            o[nv][2] *= corr_hi; o[nv][3] *= corr_hi;
        }

        // O += P V  (m16 x n64, k128).
        // A-frag = sc[kb] directly (C-frag reg r holds P[row][2tq(+1)]; with V
        // stored key-unpermuted, the float2 load supplies keys (2tq, 2tq+1)
        // in exactly the matching k-slots). Reorder: a-slots (c0,c2,c1,c3).
#pragma unroll
        for (int kb = 0; kb < 16; kb++) {
            uint32_t pa[4];
            pa[0] = __float_as_uint(sc[kb][0]);   // row g,   k-slot tq   (key 2tq)
            pa[1] = __float_as_uint(sc[kb][2]);   // row g+8, k-slot tq
            pa[2] = __float_as_uint(sc[kb][1]);   // row g,   k-slot tq+4 (key 2tq+1)
            pa[3] = __float_as_uint(sc[kb][3]);   // row g+8, k-slot tq+4
#pragma unroll
            for (int nv = 0; nv < 8; nv++) {
                const float2 vv = *(const float2*)(Vs + (nv * 8 + g) * VS_ + kb * 8 + tq * 2);
                uint32_t vb[2];
                vb[0] = __float_as_uint(vv.x);
                vb[1] = __float_as_uint(vv.y);
                mma8(o[nv], pa, vb);
            }
        }

        __syncthreads();   // all warps done reading V before overwrite
        if (kc < qc)
            attn_prefetch_v(sb + AT_VOFF,
                            g_v + head + (size_t)(kc + 1) * CHUNK_, tid);
        CP_COMMIT();
        s ^= 1;
    }

    ls_lo += __shfl_xor_sync(0xffffffffu, ls_lo, 1);
    ls_lo += __shfl_xor_sync(0xffffffffu, ls_lo, 2);
    ls_hi += __shfl_xor_sync(0xffffffffu, ls_hi, 1);
    ls_hi += __shfl_xor_sync(0xffffffffu, ls_hi, 2);
    const float il = 1.f / ls_lo, ih = 1.f / ls_hi;

    // write ctx tf32-rounded, K-permuted for the out-proj GEMM
    const int r0 = qc * CHUNK_ + m0 + g;
#pragma unroll
    for (int nv = 0; nv < 8; nv++) {
        const int col = h * HD_ + nv * 8 + 2 * tq;
        const int p0 = perm_idx(col), p1 = perm_idx(col + 1);
        float* c0 = ctx + ((size_t)b * L_ + r0) * D_;
        float* c1 = ctx + ((size_t)b * L_ + r0 + 8) * D_;
        c0[p0] = f2tff(o[nv][0] * il); c0[p1] = f2tff(o[nv][1] * il);
        c1[p0] = f2tff(o[nv][2] * ih); c1[p1] = f2tff(o[nv][3] * ih);
    }
}

// ---------------------------------------------------------------------------
extern "C" void kernel_launch(void* const* d_in, const int* in_sizes, int n_in,
                              void* d_out, int out_size)
{
    const float* x    = (const float*)d_in[0];
    const float* Wqkv = (const float*)d_in[1];
    const float* bqkv = (const float*)d_in[2];
    const float* Wout = (const float*)d_in[3];
    const float* bout = (const float*)d_in[4];
    float* out = (float*)d_out;

    (void)in_sizes; (void)n_in; (void)out_size;

    cudaFuncSetAttribute(gemm_mma_kernel, cudaFuncAttributeMaxDynamicSharedMemorySize, GEMM_SMEM);
    cudaFuncSetAttribute(attn_mma_kernel, cudaFuncAttributeMaxDynamicSharedMemorySize, ATTN_SMEM);

    float *ctx_ptr, *xr, *wqkvr, *woutr;
    cudaGetSymbolAddress((void**)&ctx_ptr, g_ctx);
    cudaGetSymbolAddress((void**)&xr, g_xr);
    cudaGetSymbolAddress((void**)&wqkvr, g_wqkvr);
    cudaGetSymbolAddress((void**)&woutr, g_woutr);

    // 0. prep: round+permute x; transpose+round+permute weights
    {
        const int n8 = M_ROWS * D_ / 8;
        roundperm_kernel<<<(n8 + 255) / 256, 256>>>((const float4*)x, (float4*)xr, n8);
        dim3 blk(32, 8);
        transperm_kernel<<<dim3(QKV_N / 32, D_ / 32), blk>>>(Wqkv, wqkvr, D_, QKV_N);
        transperm_kernel<<<dim3(D_ / 32, D_ / 32), blk>>>(Wout, woutr, D_, D_);
    }
    // 1. QKV projection + scatter: q/k [bh][l][perm(d)], v [bh][d][l]
    {
        dim3 grid(QKV_N / 128, M_ROWS / 128);   // (24, 32)
        gemm_mma_kernel<<<grid, 256, GEMM_SMEM>>>(xr, wqkvr, bqkv, nullptr,
                                                  M_ROWS, QKV_N, D_, 1);
    }
    // 2. Block-causal attention -> g_ctx (permuted, tf32-rounded)
    {
        dim3 grid(L_ / CHUNK_, B_ * H_);        // (16, 32)
        attn_mma_kernel<<<grid, 256, ATTN_SMEM>>>(ctx_ptr);
    }
    // 3. Output projection -> d_out
    {
        dim3 grid(D_ / 128, M_ROWS / 128);      // (8, 32)
        gemm_mma_kernel<<<grid, 256, GEMM_SMEM>>>(ctx_ptr, woutr, bout, out,
                                                  M_ROWS, D_, D_, 0);
    }
}